// round 9
// baseline (speedup 1.0000x reference)
#include <cuda_runtime.h>

#define NB 32
#define LL 1024
#define TT 64
#define KSEG 9
#define NCH (2 * KSEG - 2)   // 16 chains per batch

#define FMA2(d,a,b,c) asm("fma.rn.f32x2 %0, %1, %2, %3;" : "=l"(d) : "l"(a), "l"(b), "l"(c))
#define MUL2(d,a,b)   asm("mul.rn.f32x2 %0, %1, %2;"     : "=l"(d) : "l"(a), "l"(b))
#define ADD2(d,a,b)   asm("add.rn.f32x2 %0, %1, %2;"     : "=l"(d) : "l"(a), "l"(b))
#define UNPACK2(lo,hi,v) asm("mov.b64 {%0,%1}, %2;" : "=f"(lo), "=f"(hi) : "l"(v))
#define PACK2(v,lo,hi)   asm("mov.b64 %0, {%1,%2};" : "=l"(v) : "f"(lo), "f"(hi))

// segment cut points: c[k] = (k*1023)/9
__device__ __constant__ int d_cut[KSEG + 1] =
    {0, 113, 227, 341, 454, 568, 682, 795, 909, 1023};

// device-global scratch (sanctioned no-alloc scratch)
__device__ float g_vec[NB][NCH][TT];   // normalized chain output vectors
__device__ int   g_ex[NB][NCH];        // integer pow2 exponent offsets
__device__ float g_gen[NB];            // generic-path result
__device__ int   g_isgen[NB];

__global__ __launch_bounds__(128, 1)
void crf_seg_kernel(const float* __restrict__ logits,     // [B,L,T]
                    const float* __restrict__ trans,      // [T,T]
                    const float* __restrict__ start_s,    // [T]
                    const float* __restrict__ end_s,      // [T]
                    const int* __restrict__ mask)         // [B,L] bool as int32
{
    const int b    = blockIdx.x >> 2;
    const int grp  = blockIdx.x & 3;
    const int wid  = threadIdx.x >> 5;
    const int lane = threadIdx.x & 31;
    const int cid  = grp * 4 + wid;       // chain id 0..15, one per WARP
    const int j0   = 2 * lane;            // this thread's two output states
    const int j1   = 2 * lane + 1;

    // one private 64-float vector per warp; whole-warp broadcast reads
    __shared__ __align__(16) float xs_all[4][TT];
    float* xs = xs_all[wid];

    // ---- end_idx per warp (mask stored as int32), shfl-only ----
    int endi;
    {
        const int4* mb = reinterpret_cast<const int4*>(mask + (size_t)b * LL);
        int cnt = 0;
        #pragma unroll
        for (int q = 0; q < 8; ++q) {
            int4 m = mb[lane * 8 + q];
            cnt += (m.x != 0) + (m.y != 0) + (m.z != 0) + (m.w != 0);
        }
        #pragma unroll
        for (int o = 16; o > 0; o >>= 1) cnt += __shfl_xor_sync(~0u, cnt, o);
        endi = cnt - 1;
    }
    const bool generic = (endi != 1023);
    if (generic && cid != 0) return;

    const bool bwd = (!generic) && (cid >= KSEG - 1);   // cid >= 8
    const float esc = generic ? 1.0f : 0.0078125f;      // fold 2^-7 into E'

    // ---- E' in registers: e2[p][o] pairs input states (2p,2p+1) for output jo
    unsigned long long e2[32][2];
    if (!bwd) {   // columns of E: E[i][j]
        #pragma unroll
        for (int p = 0; p < 32; ++p) {
            float a0 = __expf(__ldg(&trans[(2*p    ) * TT + j0])) * esc;
            float a1 = __expf(__ldg(&trans[(2*p + 1) * TT + j0])) * esc;
            PACK2(e2[p][0], a0, a1);
            float c0 = __expf(__ldg(&trans[(2*p    ) * TT + j1])) * esc;
            float c1 = __expf(__ldg(&trans[(2*p + 1) * TT + j1])) * esc;
            PACK2(e2[p][1], c0, c1);
        }
    } else {      // rows of E: E[j][i]
        #pragma unroll
        for (int p = 0; p < 32; ++p) {
            float a0 = __expf(__ldg(&trans[j0 * TT + 2*p    ])) * esc;
            float a1 = __expf(__ldg(&trans[j0 * TT + 2*p + 1])) * esc;
            PACK2(e2[p][0], a0, a1);
            float c0 = __expf(__ldg(&trans[j1 * TT + 2*p    ])) * esc;
            float c1 = __expf(__ldg(&trans[j1 * TT + 2*p + 1])) * esc;
            PACK2(e2[p][1], c0, c1);
        }
    }

    // lgp[t*32] = logits[b][t][2*lane .. 2*lane+1]
    const float2* lgp = reinterpret_cast<const float2*>(
                            logits + (size_t)b * LL * TT) + lane;

    // full 64-input dot for this thread's two outputs
    auto dot2 = [&](float& d0, float& d1) {
        const ulonglong2* bp = reinterpret_cast<const ulonglong2*>(xs);
        unsigned long long A0,A1,A2,A3,B0,B1,B2,B3;
        {   // pairs 0..7
            ulonglong2 v0 = bp[0], v1 = bp[1], v2 = bp[2], v3 = bp[3];
            MUL2(A0, v0.x, e2[0][0]);     MUL2(B0, v0.x, e2[0][1]);
            MUL2(A1, v0.y, e2[1][0]);     MUL2(B1, v0.y, e2[1][1]);
            MUL2(A2, v1.x, e2[2][0]);     MUL2(B2, v1.x, e2[2][1]);
            MUL2(A3, v1.y, e2[3][0]);     MUL2(B3, v1.y, e2[3][1]);
            FMA2(A0, v2.x, e2[4][0], A0); FMA2(B0, v2.x, e2[4][1], B0);
            FMA2(A1, v2.y, e2[5][0], A1); FMA2(B1, v2.y, e2[5][1], B1);
            FMA2(A2, v3.x, e2[6][0], A2); FMA2(B2, v3.x, e2[6][1], B2);
            FMA2(A3, v3.y, e2[7][0], A3); FMA2(B3, v3.y, e2[7][1], B3);
        }
        {   // pairs 8..15
            ulonglong2 v0 = bp[4], v1 = bp[5], v2 = bp[6], v3 = bp[7];
            FMA2(A0, v0.x, e2[8][0],  A0); FMA2(B0, v0.x, e2[8][1],  B0);
            FMA2(A1, v0.y, e2[9][0],  A1); FMA2(B1, v0.y, e2[9][1],  B1);
            FMA2(A2, v1.x, e2[10][0], A2); FMA2(B2, v1.x, e2[10][1], B2);
            FMA2(A3, v1.y, e2[11][0], A3); FMA2(B3, v1.y, e2[11][1], B3);
            FMA2(A0, v2.x, e2[12][0], A0); FMA2(B0, v2.x, e2[12][1], B0);
            FMA2(A1, v2.y, e2[13][0], A1); FMA2(B1, v2.y, e2[13][1], B1);
            FMA2(A2, v3.x, e2[14][0], A2); FMA2(B2, v3.x, e2[14][1], B2);
            FMA2(A3, v3.y, e2[15][0], A3); FMA2(B3, v3.y, e2[15][1], B3);
        }
        {   // pairs 16..23
            ulonglong2 v0 = bp[8], v1 = bp[9], v2 = bp[10], v3 = bp[11];
            FMA2(A0, v0.x, e2[16][0], A0); FMA2(B0, v0.x, e2[16][1], B0);
            FMA2(A1, v0.y, e2[17][0], A1); FMA2(B1, v0.y, e2[17][1], B1);
            FMA2(A2, v1.x, e2[18][0], A2); FMA2(B2, v1.x, e2[18][1], B2);
            FMA2(A3, v1.y, e2[19][0], A3); FMA2(B3, v1.y, e2[19][1], B3);
            FMA2(A0, v2.x, e2[20][0], A0); FMA2(B0, v2.x, e2[20][1], B0);
            FMA2(A1, v2.y, e2[21][0], A1); FMA2(B1, v2.y, e2[21][1], B1);
            FMA2(A2, v3.x, e2[22][0], A2); FMA2(B2, v3.x, e2[22][1], B2);
            FMA2(A3, v3.y, e2[23][0], A3); FMA2(B3, v3.y, e2[23][1], B3);
        }
        {   // pairs 24..31
            ulonglong2 v0 = bp[12], v1 = bp[13], v2 = bp[14], v3 = bp[15];
            FMA2(A0, v0.x, e2[24][0], A0); FMA2(B0, v0.x, e2[24][1], B0);
            FMA2(A1, v0.y, e2[25][0], A1); FMA2(B1, v0.y, e2[25][1], B1);
            FMA2(A2, v1.x, e2[26][0], A2); FMA2(B2, v1.x, e2[26][1], B2);
            FMA2(A3, v1.y, e2[27][0], A3); FMA2(B3, v1.y, e2[27][1], B3);
            FMA2(A0, v2.x, e2[28][0], A0); FMA2(B0, v2.x, e2[28][1], B0);
            FMA2(A1, v2.y, e2[29][0], A1); FMA2(B1, v2.y, e2[29][1], B1);
            FMA2(A2, v3.x, e2[30][0], A2); FMA2(B2, v3.x, e2[30][1], B2);
            FMA2(A3, v3.y, e2[31][0], A3); FMA2(B3, v3.y, e2[31][1], B3);
        }
        ADD2(A0, A0, A1); ADD2(A2, A2, A3); ADD2(A0, A0, A2);
        ADD2(B0, B0, B1); ADD2(B2, B2, B3); ADD2(B0, B0, B2);
        float lo, hi;
        UNPACK2(lo, hi, A0); d0 = lo + hi;
        UNPACK2(lo, hi, B0); d1 = lo + hi;
    };

    auto step_fast = [&](float2 g) {
        float d0, d1;
        dot2(d0, d1);
        float y0 = d0 * __expf(g.x);
        float y1 = d1 * __expf(g.y);
        reinterpret_cast<float2*>(xs)[lane] = make_float2(y0, y1);
        __syncwarp();
    };

    auto writeout = [&](float x0, float x1, int S) {
        float bb = __shfl_sync(~0u, x0, 0);   // state 0 value
        int   ex = ((__float_as_int(bb) >> 23) & 255) - 127;
        float scale = __int_as_float((127 - ex) << 23);
        g_vec[b][cid][j0] = x0 * scale;
        g_vec[b][cid][j1] = x1 * scale;
        if (lane == 0) g_ex[b][cid] = ex + 7 * S;
    };

    if (generic) {
        // ==== correct fallback: full forward with per-step pow2 renorm ====
        float2 g0 = lgp[0];
        float v0 = __expf(g0.x + __ldg(&start_s[j0]) +
                          ((endi == 0) ? __ldg(&end_s[j0]) : 0.f));
        float v1 = __expf(g0.y + __ldg(&start_s[j1]) +
                          ((endi == 0) ? __ldg(&end_s[j1]) : 0.f));
        reinterpret_cast<float2*>(xs)[lane] = make_float2(v0, v1);
        __syncwarp();
        int exoff = 0;
        #pragma unroll 1
        for (int t = 1; t <= endi; ++t) {
            float bb = xs[0];
            int   ex = ((__float_as_int(bb) >> 23) & 255) - 127;
            float scale = __int_as_float((127 - ex) << 23);
            float2 g = lgp[(size_t)t * 32];
            float e0 = (t == endi) ? __ldg(&end_s[j0]) : 0.f;
            float e1 = (t == endi) ? __ldg(&end_s[j1]) : 0.f;
            float d0, d1;
            dot2(d0, d1);
            float y0 = d0 * (scale * __expf(g.x + e0));
            float y1 = d1 * (scale * __expf(g.y + e1));
            reinterpret_cast<float2*>(xs)[lane] = make_float2(y0, y1);
            exoff += ex;
            __syncwarp();
        }
        float2 v = reinterpret_cast<float2*>(xs)[lane];
        float s = v.x + v.y;
        #pragma unroll
        for (int o = 16; o > 0; o >>= 1) s += __shfl_xor_sync(~0u, s, o);
        if (lane == 0) {
            g_gen[b] = __int2float_rn(exoff) * 0.693147180559945f + __logf(s);
            g_isgen[b] = 1;
        }
        return;
    }
    if (cid == 0 && lane == 0) g_isgen[b] = 0;

    if (!bwd) {
        // ========== forward chains: R (cid 0), Q_k (cid k-1, k=2..8) ==========
        int lo, hi;
        if (cid == 0) {
            lo = 1; hi = d_cut[1];
            float2 g0 = lgp[0];
            float v0 = __expf(g0.x + __ldg(&start_s[j0]));
            float v1 = __expf(g0.y + __ldg(&start_s[j1]));
            reinterpret_cast<float2*>(xs)[lane] = make_float2(v0, v1);
        } else {
            int k = cid + 1;
            lo = d_cut[k - 1] + 1; hi = d_cut[k];
            reinterpret_cast<float2*>(xs)[lane] = make_float2(1.f, 1.f);
        }
        __syncwarp();

        float2 gA = lgp[(size_t)lo * 32];
        float2 gB = lgp[(size_t)(lo + 1) * 32];
        int t = lo;
        #pragma unroll 1
        for (; t + 1 <= hi; t += 2) {
            step_fast(gA); gA = lgp[(size_t)(t + 2) * 32];
            step_fast(gB); gB = lgp[(size_t)(t + 3) * 32];
        }
        if (t <= hi) step_fast(gA);

        float2 v = reinterpret_cast<float2*>(xs)[lane];   // own slot
        writeout(v.x, v.y, hi - lo + 1);
    } else {
        // ===== backward chains: P_k (cid k+6, k=2..8), W (cid 15) =====
        int lo0, hi0, S;
        if (cid == NCH - 1) {            // W
            lo0 = d_cut[KSEG - 1] + 1;   // 910
            hi0 = 1022;
            float2 g = lgp[(size_t)1023 * 32];
            float v0 = __expf(g.x + __ldg(&end_s[j0]));
            float v1 = __expf(g.y + __ldg(&end_s[j1]));
            reinterpret_cast<float2*>(xs)[lane] = make_float2(v0, v1);
            S = 1023 - d_cut[KSEG - 1];
        } else {                         // P_k
            int k = cid - 6;
            lo0 = d_cut[k - 1] + 1;
            hi0 = d_cut[k] - 1;
            float2 g = lgp[(size_t)d_cut[k] * 32];
            reinterpret_cast<float2*>(xs)[lane] =
                make_float2(__expf(g.x), __expf(g.y));
            S = d_cut[k] - d_cut[k - 1];
        }
        __syncwarp();

        float2 gA = lgp[(size_t)hi0 * 32];
        float2 gB = lgp[(size_t)(hi0 - 1) * 32];
        int t = hi0;
        #pragma unroll 1
        for (; t - 1 >= lo0; t -= 2) {
            step_fast(gA); gA = lgp[(size_t)(t - 2) * 32];
            step_fast(gB); gB = lgp[(size_t)(t - 3) * 32];
        }
        if (t >= lo0) step_fast(gA);

        float d0, d1;                    // epilogue matvec p = E' u, no pg
        dot2(d0, d1);
        writeout(d0, d1, S);
    }
}

// telescoped rank-1 combine (K-generic; q-chain scales cancel exactly):
// logZ = sum_{k=2}^{K-1}[log(p_k·x_{k-1}) − log Σq_k] + log(w·q_{K-1})
//        + ln2·(exR + exW + Σ exP_k)
__global__ void crf_combine_kernel(float* __restrict__ out)
{
    const int b = blockIdx.x;    // batch
    const int l = threadIdx.x;   // lane
    if (g_isgen[b]) { if (l == 0) out[b] = g_gen[b]; return; }

    float va[NCH], vb[NCH];
    #pragma unroll
    for (int c = 0; c < NCH; ++c) {
        va[c] = g_vec[b][c][l];
        vb[c] = g_vec[b][c][l + 32];
    }

    float acc = 0.0f;
    #pragma unroll
    for (int k = 2; k <= KSEG - 1; ++k) {
        float d = va[k + 6] * va[k - 2] + vb[k + 6] * vb[k - 2];
        float s = va[k - 1] + vb[k - 1];
        #pragma unroll
        for (int o = 16; o > 0; o >>= 1) {
            d += __shfl_xor_sync(~0u, d, o);
            s += __shfl_xor_sync(~0u, s, o);
        }
        acc += __logf(d) - __logf(s);
    }
    {
        float d = va[NCH - 1] * va[KSEG - 2] + vb[NCH - 1] * vb[KSEG - 2];
        #pragma unroll
        for (int o = 16; o > 0; o >>= 1) d += __shfl_xor_sync(~0u, d, o);
        acc += __logf(d);
    }

    if (l == 0) {
        int ex = g_ex[b][0] + g_ex[b][NCH - 1];
        #pragma unroll
        for (int c = NCH / 2; c <= NCH - 2; ++c) ex += g_ex[b][c];
        out[b] = acc + __int2float_rn(ex) * 0.693147180559945f;
    }
}

extern "C" void kernel_launch(void* const* d_in, const int* in_sizes, int n_in,
                              void* d_out, int out_size) {
    const float* logits        = (const float*)d_in[0];
    const float* transitions   = (const float*)d_in[1];
    const float* start_states  = (const float*)d_in[2];
    const float* end_states    = (const float*)d_in[3];
    const int*   mask          = (const int*)d_in[4];
    float* out = (float*)d_out;
    (void)in_sizes; (void)n_in; (void)out_size;

    crf_seg_kernel<<<NB * 4, 128>>>(logits, transitions, start_states,
                                    end_states, mask);
    crf_combine_kernel<<<NB, 32>>>(out);
}